// round 1
// baseline (speedup 1.0000x reference)
#include <cuda_runtime.h>

#define NN 8192      // L*H*W = 8*32*32
#define BB 2
#define CC 64
#define DTOT 193     // 192 val channels (v,q,k) + 1 "ones" row (for Z / bias moments)
#define NJ 49        // Taylor degrees j = 0..48

// Scratch (device globals; no allocations allowed)
__device__ float g_pq[BB][NN];
__device__ float g_pk[BB][NN];
__device__ float g_G[BB][NJ][DTOT];       // raw moments sum_n val[d,n] * t^j
__device__ float g_A[BB][CC + 1][NJ];     // coefficients M[c][j]/j! ; c==64 is Z-row

// --------------------------------------------------------------------------
// K1: pq[b,n] = sum_c q[b,c,n]*wq[c] + bq ;  pk likewise from k.
// grid: (NN/256, 2(sel), BB), block 256
// --------------------------------------------------------------------------
__global__ void proj_kernel(const float* __restrict__ q, const float* __restrict__ k,
                            const float* __restrict__ wq, const float* __restrict__ bq,
                            const float* __restrict__ wk, const float* __restrict__ bk) {
    int n   = blockIdx.x * 256 + threadIdx.x;
    int sel = blockIdx.y;
    int b   = blockIdx.z;
    const float* src = sel ? k : q;
    const float* w   = sel ? wk : wq;
    float bias       = sel ? bk[0] : bq[0];
    const float* p = src + (size_t)b * CC * NN + n;
    float s = bias;
#pragma unroll
    for (int c = 0; c < CC; c++) s += p[(size_t)c * NN] * w[c];
    if (sel) g_pk[b][n] = s;
    else     g_pq[b][n] = s;
}

// --------------------------------------------------------------------------
// K2: raw moments G[b][j][d] = sum_n val[b,d,n] * pk[b,n]^j
// One block per (b,d): 256 threads, 32 n each, 49 register accumulators.
// No atomics needed. grid: (1, DTOT, BB)
// --------------------------------------------------------------------------
__global__ void moments_kernel(const float* __restrict__ q, const float* __restrict__ k,
                               const float* __restrict__ v) {
    int d   = blockIdx.y;
    int b   = blockIdx.z;
    int tid = threadIdx.x;

    const float* src;
    if      (d < 64)  src = v + (size_t)(b * CC + d)        * NN;
    else if (d < 128) src = q + (size_t)(b * CC + (d - 64)) * NN;
    else if (d < 192) src = k + (size_t)(b * CC + (d - 128))* NN;
    else              src = nullptr;   // ones row

    float acc[NJ];
#pragma unroll
    for (int j = 0; j < NJ; j++) acc[j] = 0.f;

    const float* pk = g_pk[b];
#pragma unroll 2
    for (int n = tid; n < NN; n += 256) {
        float t = pk[n];
        float x = src ? src[n] : 1.0f;
        float p = x;
        acc[0] += p;
#pragma unroll
        for (int j = 1; j < NJ; j++) { p *= t; acc[j] += p; }
    }

    // Block reduction: warp shuffle, then cross-warp via smem
    __shared__ float red[8][NJ];
    int lane = tid & 31, warp = tid >> 5;
#pragma unroll
    for (int j = 0; j < NJ; j++) {
        float s = acc[j];
        s += __shfl_xor_sync(0xffffffffu, s, 16);
        s += __shfl_xor_sync(0xffffffffu, s, 8);
        s += __shfl_xor_sync(0xffffffffu, s, 4);
        s += __shfl_xor_sync(0xffffffffu, s, 2);
        s += __shfl_xor_sync(0xffffffffu, s, 1);
        if (lane == 0) red[warp][j] = s;
    }
    __syncthreads();
    if (tid < NJ) {
        float s = 0.f;
#pragma unroll
        for (int w = 0; w < 8; w++) s += red[w][tid];
        g_G[b][tid][d] = s;
    }
}

// --------------------------------------------------------------------------
// K2b: A[b][c][j] = (sum_d wv[c,d]*G[b][j][d] + bv[c]*G[b][j][192]) / j!
//      A[b][64][j] = G[b][j][192] / j!       (Z row)
// Double precision for the 1/j! (48! overflows fp32). Tiny kernel.
// --------------------------------------------------------------------------
__global__ void combine_kernel(const float* __restrict__ wv, const float* __restrict__ bv) {
    int b = blockIdx.x;
    for (int idx = threadIdx.x; idx < (CC + 1) * NJ; idx += blockDim.x) {
        int c = idx / NJ, j = idx % NJ;
        double fact = 1.0;
        for (int i = 2; i <= j; i++) fact *= (double)i;
        double m;
        if (c < CC) {
            double s = (double)bv[c] * (double)g_G[b][j][192];
            for (int dd = 0; dd < 192; dd++)
                s += (double)wv[c * 192 + dd] * (double)g_G[b][j][dd];
            m = s;
        } else {
            m = (double)g_G[b][j][192];
        }
        g_A[b][c][j] = (float)(m / fact);
    }
}

// --------------------------------------------------------------------------
// K3: per (b,m): s=pq[b,m]; f_c = Horner(A[c], s); Z = Horner(A[64], s)
//     out[b,c,m] = gamma * f_c / Z + v[b,c,m]
// Block = 256 threads = 64 m-lanes x 4 channel-groups. grid: (NN/64, BB)
// --------------------------------------------------------------------------
__global__ void out_kernel(const float* __restrict__ v, const float* __restrict__ gamma,
                           float* __restrict__ out) {
    __shared__ float sA[(CC + 1) * NJ];
    __shared__ float sZ[64];
    int b  = blockIdx.y;
    int mi = threadIdx.x & 63;
    int cg = threadIdx.x >> 6;
    int m  = blockIdx.x * 64 + mi;

    for (int i = threadIdx.x; i < (CC + 1) * NJ; i += 256)
        sA[i] = (&g_A[b][0][0])[i];
    __syncthreads();

    float s = g_pq[b][m];

    if (cg == 0) {
        const float* a = &sA[CC * NJ];
        float z = a[NJ - 1];
#pragma unroll
        for (int j = NJ - 2; j >= 0; j--) z = z * s + a[j];
        sZ[mi] = z;
    }
    __syncthreads();

    float gscale = gamma[0] / sZ[mi];

#pragma unroll
    for (int i = 0; i < 16; i++) {
        int c = cg + 4 * i;
        const float* a = &sA[c * NJ];
        float f = a[NJ - 1];
#pragma unroll
        for (int j = NJ - 2; j >= 0; j--) f = f * s + a[j];
        size_t idx = (size_t)(b * CC + c) * NN + m;
        out[idx] = f * gscale + v[idx];
    }
}

// --------------------------------------------------------------------------
extern "C" void kernel_launch(void* const* d_in, const int* in_sizes, int n_in,
                              void* d_out, int out_size) {
    const float* q  = (const float*)d_in[0];
    const float* k  = (const float*)d_in[1];
    const float* v  = (const float*)d_in[2];
    const float* wq = (const float*)d_in[3];
    const float* bq = (const float*)d_in[4];
    const float* wk = (const float*)d_in[5];
    const float* bk = (const float*)d_in[6];
    const float* wv = (const float*)d_in[7];
    const float* bv = (const float*)d_in[8];
    const float* gx = (const float*)d_in[9];
    float* out = (float*)d_out;

    dim3 g1(NN / 256, 2, BB);
    proj_kernel<<<g1, 256>>>(q, k, wq, bq, wk, bk);

    dim3 g2(1, DTOT, BB);
    moments_kernel<<<g2, 256>>>(q, k, v);

    combine_kernel<<<BB, 256>>>(wv, bv);

    dim3 g3(NN / 64, BB);
    out_kernel<<<g3, 256>>>(v, gx, out);
}

// round 2
// speedup vs baseline: 9.4598x; 9.4598x over previous
#include <cuda_runtime.h>

#define NN 8192      // L*H*W
#define BB 2
#define CC 64
#define NJ 48        // Taylor degrees 0..47 (remainder ~2e-10 at |st|<=12)
#define DTOT 193     // 192 val rows (v,q,k) + ones row (d=192)
#define NSPLIT 64
#define NCHUNK (NN / NSPLIT)   // 128
#define DSTRIDE 200

// Scratch (device globals; no allocations allowed)
__device__ float g_pq[BB][NN];
__device__ float g_P[BB][NJ][NN];                 // t^j / j!
__device__ float g_Gp[BB][NSPLIT][NJ][DSTRIDE];   // partial moments per n-split
__device__ float g_A[BB][CC + 1][NJ];             // poly coeffs; row CC = Z

// --------------------------------------------------------------------------
// K1: sel=0: g_pq[b][n] = <q[:,n],wq>+bq.   sel=1: t = <k[:,n],wk>+bk, then
// write scaled power table P[b][j][n] = t^j / j!  (1/j! folded in => fp32-safe)
// grid (NN/256, 2, BB), block 256
// --------------------------------------------------------------------------
__global__ void proj_pow_kernel(const float* __restrict__ q, const float* __restrict__ k,
                                const float* __restrict__ wq, const float* __restrict__ bq,
                                const float* __restrict__ wk, const float* __restrict__ bk) {
    int n   = blockIdx.x * 256 + threadIdx.x;
    int sel = blockIdx.y;
    int b   = blockIdx.z;
    const float* src = sel ? k : q;
    const float* w   = sel ? wk : wq;
    float s          = sel ? bk[0] : bq[0];
    const float* p = src + (size_t)b * CC * NN + n;
#pragma unroll
    for (int c = 0; c < CC; c++) s += p[(size_t)c * NN] * w[c];

    if (!sel) {
        g_pq[b][n] = s;
    } else {
        float pw = 1.0f;
        g_P[b][0][n] = 1.0f;
#pragma unroll
        for (int j = 1; j < NJ; j++) {
            pw *= s * (1.0f / (float)j);   // t^j / j!
            g_P[b][j][n] = pw;
        }
    }
}

// --------------------------------------------------------------------------
// K2: partial moments Gp[b][split][j][d] = sum_{n in chunk} val[d,n]*P[j,n]
// Register-tiled GEMM: block = 256 thr (td 0..31, tj 0..7), each thread owns
// 6 d (td+32k) x 6 j (tj+8jj) = 36 accumulators; lane td==0 also handles the
// ones-row d=192 for its 6 j's. smem staging, pad 33 => conflict-free.
// grid (NSPLIT, BB), block 256
// --------------------------------------------------------------------------
__global__ void __launch_bounds__(256) moments_kernel(const float* __restrict__ q,
                                                      const float* __restrict__ k,
                                                      const float* __restrict__ v) {
    __shared__ float sval[192][33];
    __shared__ float sP[NJ][33];

    int split = blockIdx.x, b = blockIdx.y;
    int tid = threadIdx.x;
    int td = tid & 31, tj = tid >> 5;
    int n0 = split * NCHUNK;

    float acc[6][6];
    float acc1[6];
#pragma unroll
    for (int kk = 0; kk < 6; kk++)
#pragma unroll
        for (int jj = 0; jj < 6; jj++) acc[kk][jj] = 0.0f;
#pragma unroll
    for (int jj = 0; jj < 6; jj++) acc1[jj] = 0.0f;

    for (int sub = 0; sub < NCHUNK / 32; sub++) {
        int ns = n0 + sub * 32;
        // stage val rows (coalesced 128B per (d) per warp-load)
        for (int i = tid; i < 192 * 32; i += 256) {
            int d = i >> 5, nn = i & 31;
            const float* srcp = (d < 64) ? v : ((d < 128) ? q : k);
            sval[d][nn] = srcp[(size_t)(b * CC + (d & 63)) * NN + ns + nn];
        }
        for (int i = tid; i < NJ * 32; i += 256) {
            int j = i >> 5, nn = i & 31;
            sP[j][nn] = g_P[b][j][ns + nn];
        }
        __syncthreads();

        for (int nn = 0; nn < 32; nn++) {
            float pj[6], xv[6];
#pragma unroll
            for (int jj = 0; jj < 6; jj++) pj[jj] = sP[tj + 8 * jj][nn];  // broadcast
#pragma unroll
            for (int kk = 0; kk < 6; kk++) xv[kk] = sval[td + 32 * kk][nn]; // conflict-free
#pragma unroll
            for (int kk = 0; kk < 6; kk++)
#pragma unroll
                for (int jj = 0; jj < 6; jj++)
                    acc[kk][jj] += xv[kk] * pj[jj];
            if (td == 0) {
#pragma unroll
                for (int jj = 0; jj < 6; jj++) acc1[jj] += pj[jj];  // ones row
            }
        }
        __syncthreads();
    }

#pragma unroll
    for (int kk = 0; kk < 6; kk++)
#pragma unroll
        for (int jj = 0; jj < 6; jj++)
            g_Gp[b][split][tj + 8 * jj][td + 32 * kk] = acc[kk][jj];
    if (td == 0) {
#pragma unroll
        for (int jj = 0; jj < 6; jj++)
            g_Gp[b][split][tj + 8 * jj][192] = acc1[jj];
    }
}

// --------------------------------------------------------------------------
// K3: reduce splits + fold wv/bv.  A[b][c][j] = bv[c]*G[j][192] + sum_d wv[c,d]G[j][d]
//     A[b][CC][j] = G[j][192]  (Z row).  All fp32 (scaling already applied).
// grid (NJ, BB), block 128
// --------------------------------------------------------------------------
__global__ void combine_kernel(const float* __restrict__ wv, const float* __restrict__ bv) {
    __shared__ float sG[DTOT];
    int j = blockIdx.x, b = blockIdx.y;
    int tid = threadIdx.x;

    for (int i = tid; i < DTOT; i += 128) {
        const float* gp = &g_Gp[b][0][j][i];
        float s0 = 0.f, s1 = 0.f, s2 = 0.f, s3 = 0.f;
#pragma unroll 4
        for (int p = 0; p < NSPLIT; p += 4) {
            s0 += gp[(size_t)(p + 0) * NJ * DSTRIDE];
            s1 += gp[(size_t)(p + 1) * NJ * DSTRIDE];
            s2 += gp[(size_t)(p + 2) * NJ * DSTRIDE];
            s3 += gp[(size_t)(p + 3) * NJ * DSTRIDE];
        }
        sG[i] = (s0 + s1) + (s2 + s3);
    }
    __syncthreads();

    int c = tid;
    if (c < CC) {
        const float* wr = wv + c * 192;
        float a0 = 0.f, a1 = 0.f, a2 = 0.f, a3 = 0.f;
#pragma unroll 4
        for (int dd = 0; dd < 192; dd += 4) {
            a0 += wr[dd + 0] * sG[dd + 0];
            a1 += wr[dd + 1] * sG[dd + 1];
            a2 += wr[dd + 2] * sG[dd + 2];
            a3 += wr[dd + 3] * sG[dd + 3];
        }
        g_A[b][c][j] = (a0 + a1) + (a2 + a3) + bv[c] * sG[192];
    } else if (c == CC) {
        g_A[b][CC][j] = sG[192];
    }
}

// --------------------------------------------------------------------------
// K4: per (b,m): s=pq[b,m]; Horner-eval f_c(s), Z(s); out = gamma*f/Z + v.
// Block 128 = 32 m x 4 channel-groups; half the channels per block (z-dim).
// Coeffs staged as float4 => 4 FMA per LDS.  grid (NN/32, BB, 2)
// --------------------------------------------------------------------------
__global__ void __launch_bounds__(128) out_kernel(const float* __restrict__ v,
                                                  const float* __restrict__ gamma,
                                                  float* __restrict__ out) {
    __shared__ float4 sA4[33][NJ / 4];   // 32 channels of this half + Z row
    __shared__ float sZ[32];
    int b = blockIdx.y, half = blockIdx.z;
    int tid = threadIdx.x;
    int mi = tid & 31, cg = tid >> 5;    // cg 0..3
    int m = blockIdx.x * 32 + mi;

    float* sA = (float*)sA4;
    for (int i = tid; i < 33 * NJ; i += 128) {
        int r = i / NJ, j = i - r * NJ;
        int c = (r < 32) ? (half * 32 + r) : CC;
        sA[r * NJ + j] = g_A[b][c][j];
    }
    __syncthreads();

    float s = g_pq[b][m];

    if (cg == 0) {
        const float4* a = sA4[32];
        float z = 0.0f;
#pragma unroll
        for (int blk = NJ / 4 - 1; blk >= 0; blk--) {
            float4 a4 = a[blk];
            z = z * s + a4.w; z = z * s + a4.z; z = z * s + a4.y; z = z * s + a4.x;
        }
        sZ[mi] = z;
    }
    __syncthreads();

    float gs = gamma[0] / sZ[mi];

#pragma unroll
    for (int i = 0; i < 8; i++) {
        int r = cg + 4 * i;
        const float4* a = sA4[r];
        float f = 0.0f;
#pragma unroll
        for (int blk = NJ / 4 - 1; blk >= 0; blk--) {
            float4 a4 = a[blk];
            f = f * s + a4.w; f = f * s + a4.z; f = f * s + a4.y; f = f * s + a4.x;
        }
        int c = half * 32 + r;
        size_t idx = (size_t)(b * CC + c) * NN + m;
        out[idx] = f * gs + v[idx];
    }
}

// --------------------------------------------------------------------------
extern "C" void kernel_launch(void* const* d_in, const int* in_sizes, int n_in,
                              void* d_out, int out_size) {
    const float* q  = (const float*)d_in[0];
    const float* k  = (const float*)d_in[1];
    const float* v  = (const float*)d_in[2];
    const float* wq = (const float*)d_in[3];
    const float* bq = (const float*)d_in[4];
    const float* wk = (const float*)d_in[5];
    const float* bk = (const float*)d_in[6];
    const float* wv = (const float*)d_in[7];
    const float* bv = (const float*)d_in[8];
    const float* gx = (const float*)d_in[9];
    float* out = (float*)d_out;

    dim3 g1(NN / 256, 2, BB);
    proj_pow_kernel<<<g1, 256>>>(q, k, wq, bq, wk, bk);

    dim3 g2(NSPLIT, BB);
    moments_kernel<<<g2, 256>>>(q, k, v);

    dim3 g3(NJ, BB);
    combine_kernel<<<g3, 128>>>(wv, bv);

    dim3 g4(NN / 32, BB, 2);
    out_kernel<<<g4, 128>>>(v, gx, out);
}

// round 3
// speedup vs baseline: 12.5968x; 1.3316x over previous
#include <cuda_runtime.h>

#define NN 8192      // L*H*W
#define BB 2
#define CC 64
#define NJ 40        // Taylor degrees 0..39 (tail ~4e-9 rel at |x|<=14)
#define DTOT 193
#define NSPLIT 64
#define NCHUNK 128   // n per moments block
#define DSTRIDE 200
#define SVPITCH 197  // gcd(197 mod 32 = 5, 32) = 1 -> conflict-free transposed tile

// Scratch (device globals; no allocations allowed)
__device__ float g_Gp[BB][NSPLIT][NJ][DSTRIDE];   // partial moments per n-split
__device__ float g_A[BB][CC + 1][NJ];             // poly coeffs; row CC = Z

// ---- f32x2 packed helpers -------------------------------------------------
__device__ __forceinline__ unsigned long long pack2(float x, float y) {
    unsigned long long r;
    asm("mov.b64 %0, {%1, %2};" : "=l"(r) : "f"(x), "f"(y));
    return r;
}
__device__ __forceinline__ float2 unpack2(unsigned long long p) {
    float2 v;
    asm("mov.b64 {%0, %1}, %2;" : "=f"(v.x), "=f"(v.y) : "l"(p));
    return v;
}
// acc = x * p + acc   (elementwise on both fp32 lanes)
#define FMA2ACC(acc, x, p) \
    asm("fma.rn.f32x2 %0, %1, %2, %0;" : "+l"(acc) : "l"(x), "l"(p))
// f = f * s + a  (Horner step)
#define HORNER2(f, s, a) \
    asm("fma.rn.f32x2 %0, %0, %1, %2;" : "+l"(f) : "l"(s), "l"(a))

// --------------------------------------------------------------------------
// K1: partial moments Gp[b][split][j][d] = sum_{n in chunk} val[d,n] * t_n^j/j!
// Fused: computes t_n = <k[:,n],wk>+bk and the scaled power table for its own
// 128-n chunk. Block 128 thr: td=tid&31 (6 d's), tj=tid>>5 (10 j's) ->
// 60 f32x2 accumulators pairing even/odd n. grid (NSPLIT, BB)
// --------------------------------------------------------------------------
__global__ void __launch_bounds__(128) moments_kernel(
        const float* __restrict__ q, const float* __restrict__ k,
        const float* __restrict__ v,
        const float* __restrict__ wk, const float* __restrict__ bk) {
    __shared__ float sval[32][SVPITCH];   // transposed: [nn][d]
    __shared__ float sP[NJ][NCHUNK];      // t^j/j! for the whole chunk
    __shared__ float swk[CC];

    int split = blockIdx.x, b = blockIdx.y;
    int tid = threadIdx.x;
    int td = tid & 31, tj = tid >> 5;     // tj in 0..3
    int n0 = split * NCHUNK;

    if (tid < CC) swk[tid] = wk[tid];
    __syncthreads();

    // t + scaled power chain for this thread's n (128 threads = 128 n)
    {
        int n = n0 + tid;
        const float* kp = k + (size_t)b * CC * NN + n;
        float t = bk[0];
#pragma unroll
        for (int c = 0; c < CC; c++) t += kp[(size_t)c * NN] * swk[c];
        float pw = 1.0f;
        sP[0][tid] = 1.0f;
#pragma unroll
        for (int j = 1; j < NJ; j++) {
            pw *= t * (1.0f / (float)j);
            sP[j][tid] = pw;
        }
    }
    __syncthreads();

    unsigned long long acc2[6][10];
#pragma unroll
    for (int kk = 0; kk < 6; kk++)
#pragma unroll
        for (int jj = 0; jj < 10; jj++) acc2[kk][jj] = 0ULL;

    for (int sub = 0; sub < NCHUNK / 32; sub++) {
        int ns = n0 + sub * 32;
        // stage 192 val rows x 32 n, transposed (coalesced LDG, conflict-free STS)
        for (int i = tid; i < 192 * 32; i += 128) {
            int d = i >> 5, nn = i & 31;
            const float* srcp = (d < 64) ? v : ((d < 128) ? q : k);
            sval[nn][d] = srcp[(size_t)(b * CC + (d & 63)) * NN + ns + nn];
        }
        __syncthreads();

        int ncb = sub * 32;
#pragma unroll 2
        for (int nn = 0; nn < 32; nn += 2) {
            unsigned long long pj2[10];
#pragma unroll
            for (int jj = 0; jj < 10; jj++)
                pj2[jj] = *(const unsigned long long*)&sP[tj + 4 * jj][ncb + nn];
            unsigned long long xv2[6];
#pragma unroll
            for (int kk = 0; kk < 6; kk++)
                xv2[kk] = pack2(sval[nn][td + 32 * kk], sval[nn + 1][td + 32 * kk]);
#pragma unroll
            for (int kk = 0; kk < 6; kk++)
#pragma unroll
                for (int jj = 0; jj < 10; jj++)
                    FMA2ACC(acc2[kk][jj], xv2[kk], pj2[jj]);
        }
        __syncthreads();
    }

#pragma unroll
    for (int kk = 0; kk < 6; kk++)
#pragma unroll
        for (int jj = 0; jj < 10; jj++) {
            float2 p = unpack2(acc2[kk][jj]);
            g_Gp[b][split][tj + 4 * jj][td + 32 * kk] = p.x + p.y;
        }

    // ones row d=192: sum of sP[j][:] over the chunk
    if (tid < NJ) {
        float s0 = 0.f, s1 = 0.f, s2 = 0.f, s3 = 0.f;
#pragma unroll 8
        for (int nn = 0; nn < NCHUNK; nn += 4) {
            s0 += sP[tid][nn + 0];
            s1 += sP[tid][nn + 1];
            s2 += sP[tid][nn + 2];
            s3 += sP[tid][nn + 3];
        }
        g_Gp[b][split][tid][192] = (s0 + s1) + (s2 + s3);
    }
}

// --------------------------------------------------------------------------
// K2: reduce splits + fold wv/bv.
// A[b][c][j] = bv[c]*G[j][192] + sum_d wv[c,d]*G[j][d];  A[b][CC][j] = G[j][192]
// grid (NJ, BB), block 128
// --------------------------------------------------------------------------
__global__ void combine_kernel(const float* __restrict__ wv, const float* __restrict__ bv) {
    __shared__ float sG[DTOT];
    int j = blockIdx.x, b = blockIdx.y;
    int tid = threadIdx.x;

    for (int i = tid; i < DTOT; i += 128) {
        const float* gp = &g_Gp[b][0][j][i];
        float s0 = 0.f, s1 = 0.f, s2 = 0.f, s3 = 0.f;
#pragma unroll 4
        for (int p = 0; p < NSPLIT; p += 4) {
            s0 += gp[(size_t)(p + 0) * NJ * DSTRIDE];
            s1 += gp[(size_t)(p + 1) * NJ * DSTRIDE];
            s2 += gp[(size_t)(p + 2) * NJ * DSTRIDE];
            s3 += gp[(size_t)(p + 3) * NJ * DSTRIDE];
        }
        sG[i] = (s0 + s1) + (s2 + s3);
    }
    __syncthreads();

    int c = tid;
    if (c < CC) {
        const float* wr = wv + c * 192;
        float a0 = 0.f, a1 = 0.f, a2 = 0.f, a3 = 0.f;
#pragma unroll 4
        for (int dd = 0; dd < 192; dd += 4) {
            a0 += wr[dd + 0] * sG[dd + 0];
            a1 += wr[dd + 1] * sG[dd + 1];
            a2 += wr[dd + 2] * sG[dd + 2];
            a3 += wr[dd + 3] * sG[dd + 3];
        }
        g_A[b][c][j] = (a0 + a1) + (a2 + a3) + bv[c] * sG[192];
    } else if (c == CC) {
        g_A[b][CC][j] = sG[192];
    }
}

// --------------------------------------------------------------------------
// K3: fused pq-projection + Horner eval + epilogue.
// Block 256 = 64 m-pairs x 4 channel-groups; each thread: 2 m (packed f32x2),
// 16 channels. Coeffs pre-duplicated {a,a} in smem -> pure FMA2 Horner.
// grid (NN/128, BB)
// --------------------------------------------------------------------------
__global__ void __launch_bounds__(256) out_kernel(
        const float* __restrict__ q, const float* __restrict__ v,
        const float* __restrict__ wq, const float* __restrict__ bq,
        const float* __restrict__ gamma, float* __restrict__ out) {
    __shared__ __align__(16) unsigned long long sAd[(CC + 1) * NJ];
    __shared__ float spq[128];
    __shared__ float sZ[128];
    __shared__ float swq[CC];

    int b = blockIdx.y;
    int tid = threadIdx.x;
    int mi = tid & 63, cg = tid >> 6;
    int base = blockIdx.x * 128;

    if (tid < CC) swq[tid] = wq[tid];
    for (int i = tid; i < (CC + 1) * NJ; i += 256) {
        float a = (&g_A[b][0][0])[i];
        sAd[i] = pack2(a, a);
    }
    __syncthreads();

    // pq for this block's 128 m's
    if (tid < 128) {
        int m = base + tid;
        const float* qp = q + (size_t)b * CC * NN + m;
        float s = bq[0];
#pragma unroll
        for (int c = 0; c < CC; c++) s += qp[(size_t)c * NN] * swq[c];
        spq[tid] = s;
    }
    __syncthreads();

    unsigned long long s2 = pack2(spq[mi], spq[mi + 64]);

    // Z for both m's of this pair (one channel-group does it)
    if (cg == 0) {
        unsigned long long f2 = 0ULL;
        const ulonglong2* a2 = (const ulonglong2*)&sAd[CC * NJ];
#pragma unroll
        for (int p = NJ / 2 - 1; p >= 0; p--) {
            ulonglong2 u = a2[p];
            HORNER2(f2, s2, u.y);
            HORNER2(f2, s2, u.x);
        }
        float2 z = unpack2(f2);
        sZ[mi] = z.x;
        sZ[mi + 64] = z.y;
    }
    __syncthreads();

    float gval = gamma[0];
    float gs0 = gval / sZ[mi];
    float gs1 = gval / sZ[mi + 64];
    int m0 = base + mi;

#pragma unroll
    for (int i = 0; i < 16; i++) {
        int c = cg * 16 + i;
        unsigned long long f2 = 0ULL;
        const ulonglong2* a2 = (const ulonglong2*)&sAd[c * NJ];
#pragma unroll
        for (int p = NJ / 2 - 1; p >= 0; p--) {
            ulonglong2 u = a2[p];
            HORNER2(f2, s2, u.y);
            HORNER2(f2, s2, u.x);
        }
        float2 f = unpack2(f2);
        size_t idx = (size_t)(b * CC + c) * NN + m0;
        out[idx]      = f.x * gs0 + v[idx];
        out[idx + 64] = f.y * gs1 + v[idx + 64];
    }
}

// --------------------------------------------------------------------------
extern "C" void kernel_launch(void* const* d_in, const int* in_sizes, int n_in,
                              void* d_out, int out_size) {
    const float* q  = (const float*)d_in[0];
    const float* k  = (const float*)d_in[1];
    const float* v  = (const float*)d_in[2];
    const float* wq = (const float*)d_in[3];
    const float* bq = (const float*)d_in[4];
    const float* wk = (const float*)d_in[5];
    const float* bk = (const float*)d_in[6];
    const float* wv = (const float*)d_in[7];
    const float* bv = (const float*)d_in[8];
    const float* gx = (const float*)d_in[9];
    float* out = (float*)d_out;

    dim3 g1(NSPLIT, BB);
    moments_kernel<<<g1, 128>>>(q, k, v, wk, bk);

    dim3 g2(NJ, BB);
    combine_kernel<<<g2, 128>>>(wv, bv);

    dim3 g3(NN / 128, BB);
    out_kernel<<<g3, 256>>>(q, v, wq, bq, gx, out);
}

// round 4
// speedup vs baseline: 14.3672x; 1.1405x over previous
#include <cuda_runtime.h>

#define NN 8192      // L*H*W
#define BB 2
#define CC 64
#define NJ 40        // Taylor degrees 0..39 (tail ~4e-9 rel at |x|<=14)
#define DTOT 193
#define NSPLIT 128
#define NCHUNK 64    // n per moments block
#define DSTRIDE 200
#define SVPITCH 197  // 197 mod 32 = 5 (odd) -> conflict-free transposed tile

typedef unsigned long long ull;

// Scratch (device globals; no allocations allowed)
__device__ float g_Gp[BB][NSPLIT][NJ][DSTRIDE];   // partial moments per n-split
__device__ float g_A[BB][CC + 1][NJ];             // poly coeffs; row CC = Z

// ---- f32x2 packed helpers -------------------------------------------------
__device__ __forceinline__ ull pack2(float x, float y) {
    ull r;
    asm("mov.b64 %0, {%1, %2};" : "=l"(r) : "f"(x), "f"(y));
    return r;
}
__device__ __forceinline__ float2 unpack2(ull p) {
    float2 v;
    asm("mov.b64 {%0, %1}, %2;" : "=f"(v.x), "=f"(v.y) : "l"(p));
    return v;
}
#define FMA2ACC(acc, x, p) \
    asm("fma.rn.f32x2 %0, %1, %2, %0;" : "+l"(acc) : "l"(x), "l"(p))
#define HORNER2(f, s, a) \
    asm("fma.rn.f32x2 %0, %0, %1, %2;" : "+l"(f) : "l"(s), "l"(a))

// --------------------------------------------------------------------------
// K1: partial moments Gp[b][split][j][d] = sum_{n in chunk} val[d,n]*t_n^j/j!
// 256 thr: td=tid&31 (6 d), tj=tid>>5 (5 j) -> 30 f32x2 accs over n-pairs.
// k-projection parallelized over all threads (16-ch partials + smem reduce).
// grid (NSPLIT, BB), 2 blocks/SM resident.
// --------------------------------------------------------------------------
__global__ void __launch_bounds__(256, 2) moments_kernel(
        const float* __restrict__ q, const float* __restrict__ k,
        const float* __restrict__ v,
        const float* __restrict__ wk, const float* __restrict__ bk) {
    __shared__ float sval[32][SVPITCH];   // transposed: [nn][d]
    __shared__ float sP[NJ][NCHUNK];      // t^j/j!
    __shared__ float sproj[4][NCHUNK];
    __shared__ float swk[CC];

    int split = blockIdx.x, b = blockIdx.y;
    int tid = threadIdx.x;
    int td = tid & 31, tj = tid >> 5;     // tj in 0..7
    int n0 = split * NCHUNK;

    if (tid < CC) swk[tid] = wk[tid];
    __syncthreads();

    // k-projection: 4 groups x 16 channels partials for 64 n
    {
        int n = tid & 63, grp = tid >> 6;
        const float* kp = k + (size_t)b * CC * NN + n0 + n;
        float s = 0.0f;
#pragma unroll
        for (int c = 0; c < 16; c++)
            s += kp[(size_t)(grp * 16 + c) * NN] * swk[grp * 16 + c];
        sproj[grp][n] = s;
    }
    __syncthreads();

    if (tid < NCHUNK) {
        float t = sproj[0][tid] + sproj[1][tid] + sproj[2][tid] + sproj[3][tid] + bk[0];
        float pw = 1.0f;
        sP[0][tid] = 1.0f;
#pragma unroll
        for (int j = 1; j < NJ; j++) {
            pw *= t * (1.0f / (float)j);
            sP[j][tid] = pw;
        }
    }
    __syncthreads();

    ull acc2[6][5];
#pragma unroll
    for (int kk = 0; kk < 6; kk++)
#pragma unroll
        for (int jj = 0; jj < 5; jj++) acc2[kk][jj] = 0ULL;

    for (int sub = 0; sub < NCHUNK / 32; sub++) {
        int ns = n0 + sub * 32;
        // stage 192 val rows x 32 n, transposed (coalesced LDG, conflict-free STS)
        for (int i = tid; i < 192 * 32; i += 256) {
            int d = i >> 5, nn = i & 31;
            const float* srcp = (d < 64) ? v : ((d < 128) ? q : k);
            sval[nn][d] = srcp[(size_t)(b * CC + (d & 63)) * NN + ns + nn];
        }
        __syncthreads();

        int ncb = sub * 32;
#pragma unroll 2
        for (int nn = 0; nn < 32; nn += 2) {
            ull pj2[5];
#pragma unroll
            for (int jj = 0; jj < 5; jj++)
                pj2[jj] = *(const ull*)&sP[tj + 8 * jj][ncb + nn];
            ull xv2[6];
#pragma unroll
            for (int kk = 0; kk < 6; kk++)
                xv2[kk] = pack2(sval[nn][td + 32 * kk], sval[nn + 1][td + 32 * kk]);
#pragma unroll
            for (int kk = 0; kk < 6; kk++)
#pragma unroll
                for (int jj = 0; jj < 5; jj++)
                    FMA2ACC(acc2[kk][jj], xv2[kk], pj2[jj]);
        }
        __syncthreads();
    }

#pragma unroll
    for (int kk = 0; kk < 6; kk++)
#pragma unroll
        for (int jj = 0; jj < 5; jj++) {
            float2 p = unpack2(acc2[kk][jj]);
            g_Gp[b][split][tj + 8 * jj][td + 32 * kk] = p.x + p.y;
        }

    // ones row d=192
    if (tid < NJ) {
        float s0 = 0.f, s1 = 0.f, s2 = 0.f, s3 = 0.f;
#pragma unroll 4
        for (int nn = 0; nn < NCHUNK; nn += 4) {
            s0 += sP[tid][nn + 0];
            s1 += sP[tid][nn + 1];
            s2 += sP[tid][nn + 2];
            s3 += sP[tid][nn + 3];
        }
        g_Gp[b][split][tid][192] = (s0 + s1) + (s2 + s3);
    }
}

// --------------------------------------------------------------------------
// K2: reduce splits + fold wv/bv.
// grid (NJ, BB), block 128
// --------------------------------------------------------------------------
__global__ void combine_kernel(const float* __restrict__ wv, const float* __restrict__ bv) {
    __shared__ float sG[DTOT];
    int j = blockIdx.x, b = blockIdx.y;
    int tid = threadIdx.x;

    for (int i = tid; i < DTOT; i += 128) {
        const float* gp = &g_Gp[b][0][j][i];
        float s0 = 0.f, s1 = 0.f, s2 = 0.f, s3 = 0.f;
#pragma unroll 4
        for (int p = 0; p < NSPLIT; p += 4) {
            s0 += gp[(size_t)(p + 0) * NJ * DSTRIDE];
            s1 += gp[(size_t)(p + 1) * NJ * DSTRIDE];
            s2 += gp[(size_t)(p + 2) * NJ * DSTRIDE];
            s3 += gp[(size_t)(p + 3) * NJ * DSTRIDE];
        }
        sG[i] = (s0 + s1) + (s2 + s3);
    }
    __syncthreads();

    int c = tid;
    if (c < CC) {
        const float* wr = wv + c * 192;
        float a0 = 0.f, a1 = 0.f, a2 = 0.f, a3 = 0.f;
#pragma unroll 4
        for (int dd = 0; dd < 192; dd += 4) {
            a0 += wr[dd + 0] * sG[dd + 0];
            a1 += wr[dd + 1] * sG[dd + 1];
            a2 += wr[dd + 2] * sG[dd + 2];
            a3 += wr[dd + 3] * sG[dd + 3];
        }
        g_A[b][c][j] = (a0 + a1) + (a2 + a3) + bv[c] * sG[192];
    } else if (c == CC) {
        g_A[b][CC][j] = sG[192];
    }
}

// --------------------------------------------------------------------------
// K3: fused pq-projection + Horner eval + epilogue.
// grid (NN/64, 2 halves, BB), block 256 = 32 m-pairs x 8 cgroups x 4 channels.
// 4 interleaved f32x2 Horner chains per thread (ILP hides fma latency).
// --------------------------------------------------------------------------
__global__ void __launch_bounds__(256) out_kernel(
        const float* __restrict__ q, const float* __restrict__ v,
        const float* __restrict__ wq, const float* __restrict__ bq,
        const float* __restrict__ gamma, float* __restrict__ out) {
    __shared__ __align__(16) ull sAd[33 * NJ];  // 32 channels of half + Z row, dup'd
    __shared__ float spq[64];
    __shared__ float sZ[64];
    __shared__ float sproj[4][64];
    __shared__ float swq[CC];

    int b = blockIdx.z, half = blockIdx.y;
    int base = blockIdx.x * 64;
    int tid = threadIdx.x;
    int mi = tid & 31, cg = tid >> 5;    // cg 0..7

    if (tid < CC) swq[tid] = wq[tid];
    for (int i = tid; i < 33 * NJ; i += 256) {
        int r = i / NJ, j = i - r * NJ;
        int c = (r < 32) ? (half * 32 + r) : CC;
        float a = g_A[b][c][j];
        sAd[i] = pack2(a, a);
    }
    __syncthreads();

    // pq projection for this block's 64 m's
    {
        int n = tid & 63, grp = tid >> 6;
        const float* qp = q + (size_t)b * CC * NN + base + n;
        float s = 0.0f;
#pragma unroll
        for (int c = 0; c < 16; c++)
            s += qp[(size_t)(grp * 16 + c) * NN] * swq[grp * 16 + c];
        sproj[grp][n] = s;
    }
    __syncthreads();
    if (tid < 64)
        spq[tid] = sproj[0][tid] + sproj[1][tid] + sproj[2][tid] + sproj[3][tid] + bq[0];
    __syncthreads();

    ull s2 = pack2(spq[mi], spq[mi + 32]);

    if (cg == 0) {
        ull f2 = 0ULL;
        const ulonglong2* a2 = (const ulonglong2*)&sAd[32 * NJ];
#pragma unroll
        for (int p = NJ / 2 - 1; p >= 0; p--) {
            ulonglong2 u = a2[p];
            HORNER2(f2, s2, u.y);
            HORNER2(f2, s2, u.x);
        }
        float2 z = unpack2(f2);
        sZ[mi] = z.x;
        sZ[mi + 32] = z.y;
    }
    __syncthreads();

    float gval = gamma[0];
    float gs0 = gval / sZ[mi];
    float gs1 = gval / sZ[mi + 32];
    int m0 = base + mi;

    // 4 interleaved Horner chains
    ull f2[4] = {0ULL, 0ULL, 0ULL, 0ULL};
    const ulonglong2* a2[4];
#pragma unroll
    for (int i = 0; i < 4; i++)
        a2[i] = (const ulonglong2*)&sAd[(cg * 4 + i) * NJ];

#pragma unroll
    for (int p = NJ / 2 - 1; p >= 0; p--) {
        ulonglong2 u0 = a2[0][p], u1 = a2[1][p], u2 = a2[2][p], u3 = a2[3][p];
        HORNER2(f2[0], s2, u0.y); HORNER2(f2[1], s2, u1.y);
        HORNER2(f2[2], s2, u2.y); HORNER2(f2[3], s2, u3.y);
        HORNER2(f2[0], s2, u0.x); HORNER2(f2[1], s2, u1.x);
        HORNER2(f2[2], s2, u2.x); HORNER2(f2[3], s2, u3.x);
    }

#pragma unroll
    for (int i = 0; i < 4; i++) {
        int c = half * 32 + cg * 4 + i;
        float2 f = unpack2(f2[i]);
        size_t idx = (size_t)(b * CC + c) * NN + m0;
        out[idx]      = f.x * gs0 + v[idx];
        out[idx + 32] = f.y * gs1 + v[idx + 32];
    }
}

// --------------------------------------------------------------------------
extern "C" void kernel_launch(void* const* d_in, const int* in_sizes, int n_in,
                              void* d_out, int out_size) {
    const float* q  = (const float*)d_in[0];
    const float* k  = (const float*)d_in[1];
    const float* v  = (const float*)d_in[2];
    const float* wq = (const float*)d_in[3];
    const float* bq = (const float*)d_in[4];
    const float* wk = (const float*)d_in[5];
    const float* bk = (const float*)d_in[6];
    const float* wv = (const float*)d_in[7];
    const float* bv = (const float*)d_in[8];
    const float* gx = (const float*)d_in[9];
    float* out = (float*)d_out;

    dim3 g1(NSPLIT, BB);
    moments_kernel<<<g1, 256>>>(q, k, v, wk, bk);

    dim3 g2(NJ, BB);
    combine_kernel<<<g2, 128>>>(wv, bv);

    dim3 g3(NN / 64, 2, BB);
    out_kernel<<<g3, 256>>>(q, v, wq, bq, gx, out);
}

// round 5
// speedup vs baseline: 15.2182x; 1.0592x over previous
#include <cuda_runtime.h>

#define NN 8192      // L*H*W
#define BB 2
#define CC 64
#define NJ 40        // Taylor degrees 0..39
#define DTOT 193
#define NSPLIT 128
#define NCHUNK 64    // n per moments block
#define DSTRIDE 200
#define SVPITCH 197  // odd pitch -> conflict-free transposed tile

typedef unsigned long long ull;

// Scratch (device globals; no allocations allowed)
__device__ float g_Gp[BB][NSPLIT][NJ][DSTRIDE];   // partial moments per n-split
__device__ float g_A[BB][CC + 1][NJ];             // poly coeffs; row CC = Z

// ---- f32x2 packed helpers -------------------------------------------------
__device__ __forceinline__ ull pack2(float x, float y) {
    ull r;
    asm("mov.b64 %0, {%1, %2};" : "=l"(r) : "f"(x), "f"(y));
    return r;
}
__device__ __forceinline__ float2 unpack2(ull p) {
    float2 v;
    asm("mov.b64 {%0, %1}, %2;" : "=f"(v.x), "=f"(v.y) : "l"(p));
    return v;
}
#define FMA2ACC(acc, x, p) \
    asm("fma.rn.f32x2 %0, %1, %2, %0;" : "+l"(acc) : "l"(x), "l"(p))
#define HORNER2(f, s, a) \
    asm("fma.rn.f32x2 %0, %0, %1, %2;" : "+l"(f) : "l"(s), "l"(a))

// --------------------------------------------------------------------------
// K1: partial moments Gp[b][split][j][d] = sum_{n in chunk} val[d,n]*t_n^j/j!
// Block 256 = 8 warps: dg = w&1 (96 d's: td+{0,32,64}+96*dg), jg = w>>1
// (10 j's: jg*10..+9). 30 f32x2 accumulators over n-pairs.
// pj loads are warp-broadcast LDS.64; sval re-read only 4x (j-groups).
// grid (NSPLIT, BB), 2 blocks/SM.
// --------------------------------------------------------------------------
__global__ void __launch_bounds__(256, 2) moments_kernel(
        const float* __restrict__ q, const float* __restrict__ k,
        const float* __restrict__ v,
        const float* __restrict__ wk, const float* __restrict__ bk) {
    __shared__ float sval[32][SVPITCH];   // transposed: [nn][d]
    __shared__ float sP[NJ][NCHUNK];      // t^j/j!
    __shared__ float sproj[4][NCHUNK];
    __shared__ float swk[CC];

    int split = blockIdx.x, b = blockIdx.y;
    int tid = threadIdx.x;
    int td = tid & 31, w = tid >> 5;
    int dbase = (w & 1) * 96;
    int jbase = (w >> 1) * 10;
    int n0 = split * NCHUNK;
    const size_t bofs = (size_t)b * CC * NN;

    if (tid < CC) swk[tid] = wk[tid];
    __syncthreads();

    // k-projection: 4 groups x 16 channels partials for 64 n
    {
        int n = tid & 63, grp = tid >> 6;
        const float* kp = k + bofs + n0 + n;
        float s = 0.0f;
#pragma unroll
        for (int c = 0; c < 16; c++)
            s += kp[(size_t)(grp * 16 + c) * NN] * swk[grp * 16 + c];
        sproj[grp][n] = s;
    }
    __syncthreads();

    if (tid < NCHUNK) {
        float t = sproj[0][tid] + sproj[1][tid] + sproj[2][tid] + sproj[3][tid] + bk[0];
        float pw = 1.0f;
        sP[0][tid] = 1.0f;
#pragma unroll
        for (int j = 1; j < NJ; j++) {
            pw *= t * (1.0f / (float)j);
            sP[j][tid] = pw;
        }
    }
    __syncthreads();

    ull acc2[3][10];
#pragma unroll
    for (int kk = 0; kk < 3; kk++)
#pragma unroll
        for (int jj = 0; jj < 10; jj++) acc2[kk][jj] = 0ULL;

    for (int sub = 0; sub < NCHUNK / 32; sub++) {
        int ns = n0 + sub * 32;
        // stage 192 val rows x 32 n, transposed (coalesced LDG, conflict-free STS)
        for (int i = tid; i < 192 * 32; i += 256) {
            int d = i >> 5, nn = i & 31;
            const float* srcp = (d < 64) ? v : ((d < 128) ? q : k);
            sval[nn][d] = srcp[bofs + (size_t)(d & 63) * NN + ns + nn];
        }
        __syncthreads();

        int ncb = sub * 32;
#pragma unroll 2
        for (int nn = 0; nn < 32; nn += 2) {
            ull pj2[10];
#pragma unroll
            for (int jj = 0; jj < 10; jj++)
                pj2[jj] = *(const ull*)&sP[jbase + jj][ncb + nn];   // broadcast
            ull xv2[3];
#pragma unroll
            for (int kk = 0; kk < 3; kk++)
                xv2[kk] = pack2(sval[nn][dbase + td + 32 * kk],
                                sval[nn + 1][dbase + td + 32 * kk]);
#pragma unroll
            for (int kk = 0; kk < 3; kk++)
#pragma unroll
                for (int jj = 0; jj < 10; jj++)
                    FMA2ACC(acc2[kk][jj], xv2[kk], pj2[jj]);
        }
        __syncthreads();
    }

#pragma unroll
    for (int kk = 0; kk < 3; kk++)
#pragma unroll
        for (int jj = 0; jj < 10; jj++) {
            float2 p = unpack2(acc2[kk][jj]);
            g_Gp[b][split][jbase + jj][dbase + td + 32 * kk] = p.x + p.y;
        }

    // ones row d=192
    if (tid < NJ) {
        float s0 = 0.f, s1 = 0.f, s2 = 0.f, s3 = 0.f;
#pragma unroll 4
        for (int nn = 0; nn < NCHUNK; nn += 4) {
            s0 += sP[tid][nn + 0];
            s1 += sP[tid][nn + 1];
            s2 += sP[tid][nn + 2];
            s3 += sP[tid][nn + 3];
        }
        g_Gp[b][split][tid][192] = (s0 + s1) + (s2 + s3);
    }
}

// --------------------------------------------------------------------------
// K2: reduce splits + fold wv/bv.  grid (NJ, BB), block 128
// --------------------------------------------------------------------------
__global__ void combine_kernel(const float* __restrict__ wv, const float* __restrict__ bv) {
    __shared__ float sG[DTOT];
    int j = blockIdx.x, b = blockIdx.y;
    int tid = threadIdx.x;

    for (int i = tid; i < DTOT; i += 128) {
        const float* gp = &g_Gp[b][0][j][i];
        float s0 = 0.f, s1 = 0.f, s2 = 0.f, s3 = 0.f;
#pragma unroll 8
        for (int p = 0; p < NSPLIT; p += 4) {
            s0 += gp[(size_t)(p + 0) * NJ * DSTRIDE];
            s1 += gp[(size_t)(p + 1) * NJ * DSTRIDE];
            s2 += gp[(size_t)(p + 2) * NJ * DSTRIDE];
            s3 += gp[(size_t)(p + 3) * NJ * DSTRIDE];
        }
        sG[i] = (s0 + s1) + (s2 + s3);
    }
    __syncthreads();

    int c = tid;
    if (c < CC) {
        const float* wr = wv + c * 192;
        float a0 = 0.f, a1 = 0.f, a2 = 0.f, a3 = 0.f;
#pragma unroll 4
        for (int dd = 0; dd < 192; dd += 4) {
            a0 += wr[dd + 0] * sG[dd + 0];
            a1 += wr[dd + 1] * sG[dd + 1];
            a2 += wr[dd + 2] * sG[dd + 2];
            a3 += wr[dd + 3] * sG[dd + 3];
        }
        g_A[b][c][j] = (a0 + a1) + (a2 + a3) + bv[c] * sG[192];
    } else if (c == CC) {
        g_A[b][CC][j] = sG[192];
    }
}

// --------------------------------------------------------------------------
// K3: fused pq-projection + Horner eval + epilogue.
// grid (NN/64, 2 halves, BB), block 256 = 32 m-pairs x 8 cgroups x 4 channels.
// 4 interleaved f32x2 Horner chains per thread.
// --------------------------------------------------------------------------
__global__ void __launch_bounds__(256) out_kernel(
        const float* __restrict__ q, const float* __restrict__ v,
        const float* __restrict__ wq, const float* __restrict__ bq,
        const float* __restrict__ gamma, float* __restrict__ out) {
    __shared__ __align__(16) ull sAd[33 * NJ];
    __shared__ float spq[64];
    __shared__ float sZ[64];
    __shared__ float sproj[4][64];
    __shared__ float swq[CC];

    int b = blockIdx.z, half = blockIdx.y;
    int base = blockIdx.x * 64;
    int tid = threadIdx.x;
    int mi = tid & 31, cg = tid >> 5;    // cg 0..7

    if (tid < CC) swq[tid] = wq[tid];
    for (int i = tid; i < 33 * NJ; i += 256) {
        int r = i / NJ, j = i - r * NJ;
        int c = (r < 32) ? (half * 32 + r) : CC;
        float a = g_A[b][c][j];
        sAd[i] = pack2(a, a);
    }
    __syncthreads();

    {
        int n = tid & 63, grp = tid >> 6;
        const float* qp = q + (size_t)b * CC * NN + base + n;
        float s = 0.0f;
#pragma unroll
        for (int c = 0; c < 16; c++)
            s += qp[(size_t)(grp * 16 + c) * NN] * swq[grp * 16 + c];
        sproj[grp][n] = s;
    }
    __syncthreads();
    if (tid < 64)
        spq[tid] = sproj[0][tid] + sproj[1][tid] + sproj[2][tid] + sproj[3][tid] + bq[0];
    __syncthreads();

    ull s2 = pack2(spq[mi], spq[mi + 32]);

    if (cg == 0) {
        ull f2 = 0ULL;
        const ulonglong2* a2 = (const ulonglong2*)&sAd[32 * NJ];
#pragma unroll
        for (int p = NJ / 2 - 1; p >= 0; p--) {
            ulonglong2 u = a2[p];
            HORNER2(f2, s2, u.y);
            HORNER2(f2, s2, u.x);
        }
        float2 z = unpack2(f2);
        sZ[mi] = z.x;
        sZ[mi + 32] = z.y;
    }
    __syncthreads();

    float gval = gamma[0];
    float gs0 = gval / sZ[mi];
    float gs1 = gval / sZ[mi + 32];
    int m0 = base + mi;

    ull f2[4] = {0ULL, 0ULL, 0ULL, 0ULL};
    const ulonglong2* a2[4];
#pragma unroll
    for (int i = 0; i < 4; i++)
        a2[i] = (const ulonglong2*)&sAd[(cg * 4 + i) * NJ];

#pragma unroll
    for (int p = NJ / 2 - 1; p >= 0; p--) {
        ulonglong2 u0 = a2[0][p], u1 = a2[1][p], u2 = a2[2][p], u3 = a2[3][p];
        HORNER2(f2[0], s2, u0.y); HORNER2(f2[1], s2, u1.y);
        HORNER2(f2[2], s2, u2.y); HORNER2(f2[3], s2, u3.y);
        HORNER2(f2[0], s2, u0.x); HORNER2(f2[1], s2, u1.x);
        HORNER2(f2[2], s2, u2.x); HORNER2(f2[3], s2, u3.x);
    }

#pragma unroll
    for (int i = 0; i < 4; i++) {
        int c = half * 32 + cg * 4 + i;
        float2 f = unpack2(f2[i]);
        size_t idx = (size_t)(b * CC + c) * NN + m0;
        out[idx]      = f.x * gs0 + v[idx];
        out[idx + 32] = f.y * gs1 + v[idx + 32];
    }
}

// --------------------------------------------------------------------------
extern "C" void kernel_launch(void* const* d_in, const int* in_sizes, int n_in,
                              void* d_out, int out_size) {
    const float* q  = (const float*)d_in[0];
    const float* k  = (const float*)d_in[1];
    const float* v  = (const float*)d_in[2];
    const float* wq = (const float*)d_in[3];
    const float* bq = (const float*)d_in[4];
    const float* wk = (const float*)d_in[5];
    const float* bk = (const float*)d_in[6];
    const float* wv = (const float*)d_in[7];
    const float* bv = (const float*)d_in[8];
    const float* gx = (const float*)d_in[9];
    float* out = (float*)d_out;

    dim3 g1(NSPLIT, BB);
    moments_kernel<<<g1, 256>>>(q, k, v, wk, bk);

    dim3 g2(NJ, BB);
    combine_kernel<<<g2, 128>>>(wv, bv);

    dim3 g3(NN / 64, 2, BB);
    out_kernel<<<g3, 256>>>(q, v, wq, bq, gx, out);
}